// round 5
// baseline (speedup 1.0000x reference)
#include <cuda_runtime.h>

typedef unsigned long long u64;

#define LAT    16
#define HID    50
#define HIDP   52          // hidden padded to multiple of 4
#define NQ     (HIDP/4)    // 13
#define TSMAX  132
#define W1T_SZ (HIDP*LAT)  // 832 floats per transposed W1 matrix

// W1 matrices (ODE + decoder), transposed to [l][i] and zero-padded, live in
// constant memory: warp-uniform loads go through the constant port instead of
// burning L1/shared wavefronts on 32-lane broadcast replication.
__constant__ float cW1t[2*W1T_SZ];   // [0]=Wo1t, [W1T_SZ]=Wd1t
__device__   float gW1t[2*W1T_SZ];   // staging (written by stage_kernel)

// ---- packed f32x2 helpers (sm_100+; ptxas never auto-fuses, PTX-only) ----
static __device__ __forceinline__ u64 pk(float lo, float hi){
    u64 r; asm("mov.b64 %0, {%1,%2};" : "=l"(r) : "f"(lo), "f"(hi)); return r;
}
static __device__ __forceinline__ void upk(u64 v, float& lo, float& hi){
    asm("mov.b64 {%0,%1}, %2;" : "=f"(lo), "=f"(hi) : "l"(v));
}
static __device__ __forceinline__ u64 dup2(float x){ return pk(x, x); }
static __device__ __forceinline__ u64 fma2(u64 a, u64 b, u64 c){
    u64 d; asm("fma.rn.f32x2 %0, %1, %2, %3;" : "=l"(d) : "l"(a), "l"(b), "l"(c)); return d;
}
static __device__ __forceinline__ u64 add2(u64 a, u64 b){
    u64 d; asm("add.rn.f32x2 %0, %1, %2;" : "=l"(d) : "l"(a), "l"(b)); return d;
}
static __device__ __forceinline__ float hsum(u64 v){
    float lo, hi; upk(v, lo, hi); return lo + hi;
}

// tanh(x) = 1 - 2/(exp(2x)+1); ex2.approx + rcp.approx -> ~1e-7 rel err
static __device__ __forceinline__ float tanh_fast(float x){
    float e, r;
    float y = x * 2.88539008177792681472f;   // 2*log2(e)
    asm("ex2.approx.f32 %0, %1;" : "=f"(e) : "f"(y));
    float d = e + 1.0f;
    asm("rcp.approx.f32 %0, %1;" : "=f"(r) : "f"(d));
    return fmaf(-2.0f, r, 1.0f);
}

// o = tanh(z @ W1 + b1) @ W2 + b2
// zp[8] : state packed over latent dim; W1t from __constant__ at offset WOFF
template<int WOFF>
static __device__ __forceinline__ void ode_f(const u64* __restrict__ zp,
                                             u64* __restrict__ o,
                                             const float* __restrict__ sb1,
                                             const float* __restrict__ sW2,
                                             const float* __restrict__ sb2)
{
    #pragma unroll
    for (int p = 0; p < 8; ++p) o[p] = *(const u64*)(sb2 + 2*p);

    #pragma unroll 1
    for (int lq = 0; lq < NQ; ++lq){
        const int l = lq * 4;
        u64 p0 = 0, p1 = 0, p2 = 0, p3 = 0;
        const int base = WOFF + l*LAT;
        #pragma unroll
        for (int q = 0; q < 4; ++q){
            const ulonglong2 w0 = *(const ulonglong2*)&cW1t[base           + 4*q];
            const ulonglong2 w1 = *(const ulonglong2*)&cW1t[base +   LAT   + 4*q];
            const ulonglong2 w2 = *(const ulonglong2*)&cW1t[base + 2*LAT   + 4*q];
            const ulonglong2 w3 = *(const ulonglong2*)&cW1t[base + 3*LAT   + 4*q];
            p0 = fma2(zp[2*q], w0.x, p0); p0 = fma2(zp[2*q+1], w0.y, p0);
            p1 = fma2(zp[2*q], w1.x, p1); p1 = fma2(zp[2*q+1], w1.y, p1);
            p2 = fma2(zp[2*q], w2.x, p2); p2 = fma2(zp[2*q+1], w2.y, p2);
            p3 = fma2(zp[2*q], w3.x, p3); p3 = fma2(zp[2*q+1], w3.y, p3);
        }
        const float4 b = *(const float4*)(sb1 + l);
        float hh[4];
        hh[0] = tanh_fast(hsum(p0) + b.x);
        hh[1] = tanh_fast(hsum(p1) + b.y);
        hh[2] = tanh_fast(hsum(p2) + b.z);
        hh[3] = tanh_fast(hsum(p3) + b.w);
        #pragma unroll
        for (int r4 = 0; r4 < 4; ++r4){
            const u64 hd = dup2(hh[r4]);
            const float* wr = sW2 + (l + r4)*LAT;
            #pragma unroll
            for (int q = 0; q < 4; ++q){
                const ulonglong2 w = *(const ulonglong2*)(wr + 4*q);
                o[2*q]     = fma2(hd, w.x, o[2*q]);
                o[2*q + 1] = fma2(hd, w.y, o[2*q + 1]);
            }
        }
    }
}

// y = relu(z @ Wd1 + bd1) @ Wd2 + bd2  (scalar output); Wd1t in constant
static __device__ __forceinline__ float dec_f(const u64* __restrict__ zp,
                                              const float* __restrict__ sb1,
                                              const float* __restrict__ sw2,
                                              float b2)
{
    float y = b2;
    #pragma unroll 1
    for (int lq = 0; lq < NQ; ++lq){
        const int l = lq * 4;
        u64 p0 = 0, p1 = 0, p2 = 0, p3 = 0;
        const int base = W1T_SZ + l*LAT;
        #pragma unroll
        for (int q = 0; q < 4; ++q){
            const ulonglong2 w0 = *(const ulonglong2*)&cW1t[base           + 4*q];
            const ulonglong2 w1 = *(const ulonglong2*)&cW1t[base +   LAT   + 4*q];
            const ulonglong2 w2 = *(const ulonglong2*)&cW1t[base + 2*LAT   + 4*q];
            const ulonglong2 w3 = *(const ulonglong2*)&cW1t[base + 3*LAT   + 4*q];
            p0 = fma2(zp[2*q], w0.x, p0); p0 = fma2(zp[2*q+1], w0.y, p0);
            p1 = fma2(zp[2*q], w1.x, p1); p1 = fma2(zp[2*q+1], w1.y, p1);
            p2 = fma2(zp[2*q], w2.x, p2); p2 = fma2(zp[2*q+1], w2.y, p2);
            p3 = fma2(zp[2*q], w3.x, p3); p3 = fma2(zp[2*q+1], w3.y, p3);
        }
        const float4 b  = *(const float4*)(sb1 + l);
        const float4 w2 = *(const float4*)(sw2 + l);
        y = fmaf(fmaxf(hsum(p0) + b.x, 0.f), w2.x, y);
        y = fmaf(fmaxf(hsum(p1) + b.y, 0.f), w2.y, y);
        y = fmaf(fmaxf(hsum(p2) + b.z, 0.f), w2.z, y);
        y = fmaf(fmaxf(hsum(p3) + b.w, 0.f), w2.w, y);
    }
    return y;
}

// Staging: build transposed + zero-padded W1 matrices in a __device__ array;
// host side then copies them into __constant__ (DtoD, graph-capturable).
__global__ void stage_kernel(const float* __restrict__ Wo1,
                             const float* __restrict__ Wd1)
{
    const int idx = blockIdx.x * blockDim.x + threadIdx.x;
    if (idx < W1T_SZ){
        const int l = idx / LAT, i = idx - l*LAT;
        const bool v = (l < HID);
        gW1t[idx]          = v ? Wo1[i*HID + l] : 0.f;
        gW1t[W1T_SZ + idx] = v ? Wd1[i*HID + l] : 0.f;
    }
}

__global__ void __launch_bounds__(64, 6) node_kernel(
    const float* __restrict__ x0,  const float* __restrict__ ts,
    const float* __restrict__ We1, const float* __restrict__ be1,
    const float* __restrict__ We2, const float* __restrict__ be2,
    const float* __restrict__ bo1, const float* __restrict__ Wo2,
    const float* __restrict__ bo2, const float* __restrict__ bd1,
    const float* __restrict__ Wd2, const float* __restrict__ bd2,
    float* __restrict__ out, int B, int T)
{
    __shared__ __align__(16) float sWo2 [HIDP*LAT];  // [l][j]
    __shared__ __align__(16) float sWe2 [HIDP*LAT];  // [l][j]
    __shared__ __align__(16) float sWe1 [2*HIDP];
    __shared__ __align__(16) float sbo1 [HIDP];
    __shared__ __align__(16) float sbd1 [HIDP];
    __shared__ __align__(16) float sbe1 [HIDP];
    __shared__ __align__(16) float sWd2 [HIDP];
    __shared__ __align__(16) float sbo2 [LAT];
    __shared__ __align__(16) float sbe2 [LAT];
    __shared__ __align__(16) u64   sKsum[8*64];      // per-thread RK accumulator
    __shared__ float sT[TSMAX];

    const int tid = threadIdx.x, bs = blockDim.x;

    for (int idx = tid; idx < HIDP*LAT; idx += bs){
        const int l = idx / LAT, i = idx - l*LAT;
        const bool v = (l < HID);
        sWo2[idx] = v ? Wo2[l*LAT + i] : 0.f;
        sWe2[idx] = v ? We2[l*LAT + i] : 0.f;
    }
    for (int idx = tid; idx < HIDP; idx += bs){
        const bool v = (idx < HID);
        sbo1[idx] = v ? bo1[idx] : 0.f;
        sbd1[idx] = v ? bd1[idx] : 0.f;
        sbe1[idx] = v ? be1[idx] : 0.f;
        sWd2[idx] = v ? Wd2[idx] : 0.f;
        sWe1[idx]        = v ? We1[idx]       : 0.f;  // row 0 of (2,HID)
        sWe1[HIDP + idx] = v ? We1[HID + idx] : 0.f;  // row 1
    }
    if (tid < LAT){ sbo2[tid] = bo2[tid]; sbe2[tid] = be2[tid]; }
    const int tcap = (T < TSMAX) ? T : TSMAX;
    for (int idx = tid; idx < tcap; idx += bs) sT[idx] = ts[idx];
    __syncthreads();

    const int b = blockIdx.x * bs + tid;
    if (b >= B) return;

    // ---- encoder: z0 = relu(x0 @ We1 + be1) @ We2 + be2 (packed over latent) ----
    const float2 xv = *(const float2*)(x0 + 2*b);
    u64 z[8];
    #pragma unroll
    for (int p = 0; p < 8; ++p) z[p] = *(const u64*)(sbe2 + 2*p);
    #pragma unroll 1
    for (int l = 0; l < HID; ++l){
        const float h = fmaxf(fmaf(xv.x, sWe1[l], fmaf(xv.y, sWe1[HIDP + l], sbe1[l])), 0.f);
        const u64 hd = dup2(h);
        const float* wr = sWe2 + l*LAT;
        #pragma unroll
        for (int q = 0; q < 4; ++q){
            const ulonglong2 w2 = *(const ulonglong2*)(wr + 4*q);
            z[2*q]     = fma2(hd, w2.x, z[2*q]);
            z[2*q + 1] = fma2(hd, w2.y, z[2*q + 1]);
        }
    }

    u64 zs[8], kk[8];
    u64* ksp = &sKsum[tid];           // element p at ksp[p*64]
    const float bd2v = bd2[0];
    float* outp = out + b;
    const u64 two = dup2(2.0f);

    #pragma unroll 1
    for (int t = 0; t < T; ++t){
        outp[(size_t)t * B] = dec_f(z, sbd1, sWd2, bd2v);
        if (t == T - 1) break;

        const float dt = (t + 1 < tcap) ? (sT[t+1] - sT[t]) : (ts[t+1] - ts[t]);
        const u64 hdt = dup2(0.5f * dt);
        const u64 fdt = dup2(dt);
        const u64 sdt = dup2(dt * (1.0f/6.0f));

        ode_f<0>(z,  kk, sbo1, sWo2, sbo2);                 // k1
        #pragma unroll
        for (int p = 0; p < 8; ++p){ ksp[p*64] = kk[p]; zs[p] = fma2(hdt, kk[p], z[p]); }
        ode_f<0>(zs, kk, sbo1, sWo2, sbo2);                 // k2
        #pragma unroll
        for (int p = 0; p < 8; ++p){ ksp[p*64] = fma2(two, kk[p], ksp[p*64]); zs[p] = fma2(hdt, kk[p], z[p]); }
        ode_f<0>(zs, kk, sbo1, sWo2, sbo2);                 // k3
        #pragma unroll
        for (int p = 0; p < 8; ++p){ ksp[p*64] = fma2(two, kk[p], ksp[p*64]); zs[p] = fma2(fdt, kk[p], z[p]); }
        ode_f<0>(zs, kk, sbo1, sWo2, sbo2);                 // k4
        #pragma unroll
        for (int p = 0; p < 8; ++p){ z[p] = fma2(sdt, add2(ksp[p*64], kk[p]), z[p]); }
    }
}

extern "C" void kernel_launch(void* const* d_in, const int* in_sizes, int n_in,
                              void* d_out, int out_size)
{
    const float* x0  = (const float*)d_in[0];
    const float* ts  = (const float*)d_in[1];
    const float* We1 = (const float*)d_in[2];
    const float* be1 = (const float*)d_in[3];
    const float* We2 = (const float*)d_in[4];
    const float* be2 = (const float*)d_in[5];
    const float* Wo1 = (const float*)d_in[6];
    const float* bo1 = (const float*)d_in[7];
    const float* Wo2 = (const float*)d_in[8];
    const float* bo2 = (const float*)d_in[9];
    const float* Wd1 = (const float*)d_in[10];
    const float* bd1 = (const float*)d_in[11];
    const float* Wd2 = (const float*)d_in[12];
    const float* bd2 = (const float*)d_in[13];

    const int B = in_sizes[0] / 2;   // (B, 2)
    const int T = in_sizes[1];       // (T,)

    // 1) build transposed/padded W1 matrices in device staging
    stage_kernel<<<(W1T_SZ + 127)/128, 128>>>(Wo1, Wd1);

    // 2) staging -> __constant__ (DtoD async memcpy; graph-capturable, no alloc)
    void* gptr = nullptr;
    cudaGetSymbolAddress(&gptr, gW1t);
    cudaMemcpyToSymbolAsync(cW1t, gptr, sizeof(float)*2*W1T_SZ, 0,
                            cudaMemcpyDeviceToDevice, 0);

    // 3) main kernel
    const int bs = 64;
    const int grid = (B + bs - 1) / bs;
    node_kernel<<<grid, bs>>>(x0, ts, We1, be1, We2, be2, bo1, Wo2,
                              bo2, bd1, Wd2, bd2, (float*)d_out, B, T);
}

// round 6
// speedup vs baseline: 1.0708x; 1.0708x over previous
#include <cuda_runtime.h>

typedef unsigned long long u64;

#define LAT   16
#define HID   50
#define HIDP  52          // hidden padded to multiple of 4
#define NQ    (HIDP/4)    // 13
#define TSMAX 132
#define BS    32          // threads per CTA (1 warp)

// ---- packed f32x2 helpers (sm_100+; PTX-only, ptxas never auto-fuses) ----
static __device__ __forceinline__ u64 pk(float lo, float hi){
    u64 r; asm("mov.b64 %0, {%1,%2};" : "=l"(r) : "f"(lo), "f"(hi)); return r;
}
static __device__ __forceinline__ void upk(u64 v, float& lo, float& hi){
    asm("mov.b64 {%0,%1}, %2;" : "=f"(lo), "=f"(hi) : "l"(v));
}
static __device__ __forceinline__ u64 dup2(float x){ return pk(x, x); }
static __device__ __forceinline__ u64 fma2(u64 a, u64 b, u64 c){
    u64 d; asm("fma.rn.f32x2 %0, %1, %2, %3;" : "=l"(d) : "l"(a), "l"(b), "l"(c)); return d;
}
static __device__ __forceinline__ u64 add2(u64 a, u64 b){
    u64 d; asm("add.rn.f32x2 %0, %1, %2;" : "=l"(d) : "l"(a), "l"(b)); return d;
}
static __device__ __forceinline__ float hsum(u64 v){
    float lo, hi; upk(v, lo, hi); return lo + hi;
}

// tanh(x) = 1 - 2/(exp(2x)+1); ex2.approx + rcp.approx -> ~1e-7 rel err
static __device__ __forceinline__ float tanh_fast(float x){
    float e, r;
    float y = x * 2.88539008177792681472f;   // 2*log2(e)
    asm("ex2.approx.f32 %0, %1;" : "=f"(e) : "f"(y));
    float d = e + 1.0f;
    asm("rcp.approx.f32 %0, %1;" : "=f"(r) : "f"(d));
    return fmaf(-2.0f, r, 1.0f);
}

// Dual-element ODE func: o = tanh(z @ W1 + b1) @ W2 + b2 for two states,
// sharing every weight load between them (each LDS.128 feeds 4 FFMA2).
static __device__ __forceinline__ void ode_f2(
    const u64* __restrict__ za, const u64* __restrict__ zb,
    u64* __restrict__ oa, u64* __restrict__ ob,
    const float* __restrict__ sW1t,   // [HIDP][LAT] transposed
    const float* __restrict__ sb1,
    const float* __restrict__ sW2,    // [HIDP][LAT]
    const float* __restrict__ sb2)
{
    #pragma unroll
    for (int p = 0; p < 8; ++p){ oa[p] = *(const u64*)(sb2 + 2*p); ob[p] = oa[p]; }

    #pragma unroll 1
    for (int lq = 0; lq < NQ; ++lq){
        const int l = lq * 4;
        u64 pa0=0, pa1=0, pa2=0, pa3=0;
        u64 pb0=0, pb1=0, pb2=0, pb3=0;
        const float* r = sW1t + l*LAT;
        #pragma unroll
        for (int q = 0; q < 4; ++q){
            const ulonglong2 w0 = *(const ulonglong2*)(r           + 4*q);
            const ulonglong2 w1 = *(const ulonglong2*)(r +   LAT   + 4*q);
            const ulonglong2 w2 = *(const ulonglong2*)(r + 2*LAT   + 4*q);
            const ulonglong2 w3 = *(const ulonglong2*)(r + 3*LAT   + 4*q);
            pa0 = fma2(za[2*q], w0.x, pa0); pa0 = fma2(za[2*q+1], w0.y, pa0);
            pb0 = fma2(zb[2*q], w0.x, pb0); pb0 = fma2(zb[2*q+1], w0.y, pb0);
            pa1 = fma2(za[2*q], w1.x, pa1); pa1 = fma2(za[2*q+1], w1.y, pa1);
            pb1 = fma2(zb[2*q], w1.x, pb1); pb1 = fma2(zb[2*q+1], w1.y, pb1);
            pa2 = fma2(za[2*q], w2.x, pa2); pa2 = fma2(za[2*q+1], w2.y, pa2);
            pb2 = fma2(zb[2*q], w2.x, pb2); pb2 = fma2(zb[2*q+1], w2.y, pb2);
            pa3 = fma2(za[2*q], w3.x, pa3); pa3 = fma2(za[2*q+1], w3.y, pa3);
            pb3 = fma2(zb[2*q], w3.x, pb3); pb3 = fma2(zb[2*q+1], w3.y, pb3);
        }
        const float4 b = *(const float4*)(sb1 + l);
        float ha[4], hb[4];
        ha[0] = tanh_fast(hsum(pa0) + b.x);  hb[0] = tanh_fast(hsum(pb0) + b.x);
        ha[1] = tanh_fast(hsum(pa1) + b.y);  hb[1] = tanh_fast(hsum(pb1) + b.y);
        ha[2] = tanh_fast(hsum(pa2) + b.z);  hb[2] = tanh_fast(hsum(pb2) + b.z);
        ha[3] = tanh_fast(hsum(pa3) + b.w);  hb[3] = tanh_fast(hsum(pb3) + b.w);
        #pragma unroll
        for (int r4 = 0; r4 < 4; ++r4){
            const u64 hda = dup2(ha[r4]);
            const u64 hdb = dup2(hb[r4]);
            const float* wr = sW2 + (l + r4)*LAT;
            #pragma unroll
            for (int q = 0; q < 4; ++q){
                const ulonglong2 w = *(const ulonglong2*)(wr + 4*q);
                oa[2*q]     = fma2(hda, w.x, oa[2*q]);
                oa[2*q + 1] = fma2(hda, w.y, oa[2*q + 1]);
                ob[2*q]     = fma2(hdb, w.x, ob[2*q]);
                ob[2*q + 1] = fma2(hdb, w.y, ob[2*q + 1]);
            }
        }
    }
}

// Dual-element decoder: y = relu(z @ Wd1 + bd1) @ Wd2 + bd2
static __device__ __forceinline__ void dec_f2(
    const u64* __restrict__ za, const u64* __restrict__ zb,
    float& ya, float& yb,
    const float* __restrict__ sW1t, const float* __restrict__ sb1,
    const float* __restrict__ sw2, float b2)
{
    ya = b2; yb = b2;
    #pragma unroll 1
    for (int lq = 0; lq < NQ; ++lq){
        const int l = lq * 4;
        u64 pa0=0, pa1=0, pa2=0, pa3=0;
        u64 pb0=0, pb1=0, pb2=0, pb3=0;
        const float* r = sW1t + l*LAT;
        #pragma unroll
        for (int q = 0; q < 4; ++q){
            const ulonglong2 w0 = *(const ulonglong2*)(r           + 4*q);
            const ulonglong2 w1 = *(const ulonglong2*)(r +   LAT   + 4*q);
            const ulonglong2 w2 = *(const ulonglong2*)(r + 2*LAT   + 4*q);
            const ulonglong2 w3 = *(const ulonglong2*)(r + 3*LAT   + 4*q);
            pa0 = fma2(za[2*q], w0.x, pa0); pa0 = fma2(za[2*q+1], w0.y, pa0);
            pb0 = fma2(zb[2*q], w0.x, pb0); pb0 = fma2(zb[2*q+1], w0.y, pb0);
            pa1 = fma2(za[2*q], w1.x, pa1); pa1 = fma2(za[2*q+1], w1.y, pa1);
            pb1 = fma2(zb[2*q], w1.x, pb1); pb1 = fma2(zb[2*q+1], w1.y, pb1);
            pa2 = fma2(za[2*q], w2.x, pa2); pa2 = fma2(za[2*q+1], w2.y, pa2);
            pb2 = fma2(zb[2*q], w2.x, pb2); pb2 = fma2(zb[2*q+1], w2.y, pb2);
            pa3 = fma2(za[2*q], w3.x, pa3); pa3 = fma2(za[2*q+1], w3.y, pa3);
            pb3 = fma2(zb[2*q], w3.x, pb3); pb3 = fma2(zb[2*q+1], w3.y, pb3);
        }
        const float4 b  = *(const float4*)(sb1 + l);
        const float4 w2 = *(const float4*)(sw2 + l);
        ya = fmaf(fmaxf(hsum(pa0) + b.x, 0.f), w2.x, ya);
        yb = fmaf(fmaxf(hsum(pb0) + b.x, 0.f), w2.x, yb);
        ya = fmaf(fmaxf(hsum(pa1) + b.y, 0.f), w2.y, ya);
        yb = fmaf(fmaxf(hsum(pb1) + b.y, 0.f), w2.y, yb);
        ya = fmaf(fmaxf(hsum(pa2) + b.z, 0.f), w2.z, ya);
        yb = fmaf(fmaxf(hsum(pb2) + b.z, 0.f), w2.z, yb);
        ya = fmaf(fmaxf(hsum(pa3) + b.w, 0.f), w2.w, ya);
        yb = fmaf(fmaxf(hsum(pb3) + b.w, 0.f), w2.w, yb);
    }
}

__global__ void __launch_bounds__(BS, 8) node_kernel(
    const float* __restrict__ x0,  const float* __restrict__ ts,
    const float* __restrict__ We1, const float* __restrict__ be1,
    const float* __restrict__ We2, const float* __restrict__ be2,
    const float* __restrict__ Wo1, const float* __restrict__ bo1,
    const float* __restrict__ Wo2, const float* __restrict__ bo2,
    const float* __restrict__ Wd1, const float* __restrict__ bd1,
    const float* __restrict__ Wd2, const float* __restrict__ bd2,
    float* __restrict__ out, int B, int T)
{
    __shared__ __align__(16) float sWo1t[HIDP*LAT];  // [l][i] transposed
    __shared__ __align__(16) float sWo2 [HIDP*LAT];  // [l][j]
    __shared__ __align__(16) float sWd1t[HIDP*LAT];  // [l][i] transposed
    __shared__ __align__(16) float sWe2 [HIDP*LAT];  // [l][j]
    __shared__ __align__(16) float sWe1 [2*HIDP];
    __shared__ __align__(16) float sbo1 [HIDP];
    __shared__ __align__(16) float sbd1 [HIDP];
    __shared__ __align__(16) float sbe1 [HIDP];
    __shared__ __align__(16) float sWd2 [HIDP];
    __shared__ __align__(16) float sbo2 [LAT];
    __shared__ __align__(16) float sbe2 [LAT];
    __shared__ __align__(16) u64   sZ[16*BS];        // per-thread z state (2 elems)
    __shared__ float sT[TSMAX];

    const int tid = threadIdx.x;

    for (int idx = tid; idx < HIDP*LAT; idx += BS){
        const int l = idx / LAT, i = idx - l*LAT;
        const bool v = (l < HID);
        sWo1t[idx] = v ? Wo1[i*HID + l] : 0.f;        // transpose
        sWd1t[idx] = v ? Wd1[i*HID + l] : 0.f;        // transpose
        sWo2 [idx] = v ? Wo2[l*LAT + i] : 0.f;
        sWe2 [idx] = v ? We2[l*LAT + i] : 0.f;
    }
    for (int idx = tid; idx < HIDP; idx += BS){
        const bool v = (idx < HID);
        sbo1[idx] = v ? bo1[idx] : 0.f;
        sbd1[idx] = v ? bd1[idx] : 0.f;
        sbe1[idx] = v ? be1[idx] : 0.f;
        sWd2[idx] = v ? Wd2[idx] : 0.f;
        sWe1[idx]        = v ? We1[idx]       : 0.f;  // row 0 of (2,HID)
        sWe1[HIDP + idx] = v ? We1[HID + idx] : 0.f;  // row 1
    }
    if (tid < LAT){ sbo2[tid] = bo2[tid]; sbe2[tid] = be2[tid]; }
    const int tcap = (T < TSMAX) ? T : TSMAX;
    for (int idx = tid; idx < tcap; idx += BS) sT[idx] = ts[idx];
    __syncthreads();

    const int half = B >> 1;
    const int b0 = blockIdx.x * BS + tid;
    if (b0 >= half) return;
    const int b1 = b0 + half;

    u64* zpa = &sZ[tid];            // elem-a state p at zpa[p*BS]
    u64* zpb = &sZ[8*BS + tid];     // elem-b state p at zpb[p*BS]

    // ---- encoder for both elements (shared weight loads) ----
    {
        const float2 xa = *(const float2*)(x0 + 2*b0);
        const float2 xb = *(const float2*)(x0 + 2*b1);
        u64 ea[8], eb[8];
        #pragma unroll
        for (int p = 0; p < 8; ++p){ ea[p] = *(const u64*)(sbe2 + 2*p); eb[p] = ea[p]; }
        #pragma unroll 1
        for (int l = 0; l < HID; ++l){
            const float w0 = sWe1[l], w1 = sWe1[HIDP + l], bb = sbe1[l];
            const float hA = fmaxf(fmaf(xa.x, w0, fmaf(xa.y, w1, bb)), 0.f);
            const float hB = fmaxf(fmaf(xb.x, w0, fmaf(xb.y, w1, bb)), 0.f);
            const u64 hda = dup2(hA), hdb = dup2(hB);
            const float* wr = sWe2 + l*LAT;
            #pragma unroll
            for (int q = 0; q < 4; ++q){
                const ulonglong2 w2 = *(const ulonglong2*)(wr + 4*q);
                ea[2*q]     = fma2(hda, w2.x, ea[2*q]);
                ea[2*q + 1] = fma2(hda, w2.y, ea[2*q + 1]);
                eb[2*q]     = fma2(hdb, w2.x, eb[2*q]);
                eb[2*q + 1] = fma2(hdb, w2.y, eb[2*q + 1]);
            }
        }
        #pragma unroll
        for (int p = 0; p < 8; ++p){ zpa[p*BS] = ea[p]; zpb[p*BS] = eb[p]; }
    }

    u64 za[8], zb[8], ka[8], kb[8], ksa[8], ksb[8];
    const float bd2v = bd2[0];
    float* outp = out;
    const u64 two = dup2(2.0f);

    #pragma unroll 1
    for (int t = 0; t < T; ++t){
        #pragma unroll
        for (int p = 0; p < 8; ++p){ za[p] = zpa[p*BS]; zb[p] = zpb[p*BS]; }

        float ya, yb;
        dec_f2(za, zb, ya, yb, sWd1t, sbd1, sWd2, bd2v);
        outp[(size_t)t * B + b0] = ya;
        outp[(size_t)t * B + b1] = yb;
        if (t == T - 1) break;

        const float dt = (t + 1 < tcap) ? (sT[t+1] - sT[t]) : (ts[t+1] - ts[t]);
        const u64 hdt = dup2(0.5f * dt);
        const u64 fdt = dup2(dt);
        const u64 sdt = dup2(dt * (1.0f/6.0f));

        ode_f2(za, zb, ka, kb, sWo1t, sbo1, sWo2, sbo2);           // k1
        #pragma unroll
        for (int p = 0; p < 8; ++p){
            ksa[p] = ka[p];                 ksb[p] = kb[p];
            za[p] = fma2(hdt, ka[p], za[p]); zb[p] = fma2(hdt, kb[p], zb[p]);
        }
        ode_f2(za, zb, ka, kb, sWo1t, sbo1, sWo2, sbo2);           // k2
        #pragma unroll
        for (int p = 0; p < 8; ++p){
            ksa[p] = fma2(two, ka[p], ksa[p]); ksb[p] = fma2(two, kb[p], ksb[p]);
            za[p] = fma2(hdt, ka[p], zpa[p*BS]); zb[p] = fma2(hdt, kb[p], zpb[p*BS]);
        }
        ode_f2(za, zb, ka, kb, sWo1t, sbo1, sWo2, sbo2);           // k3
        #pragma unroll
        for (int p = 0; p < 8; ++p){
            ksa[p] = fma2(two, ka[p], ksa[p]); ksb[p] = fma2(two, kb[p], ksb[p]);
            za[p] = fma2(fdt, ka[p], zpa[p*BS]); zb[p] = fma2(fdt, kb[p], zpb[p*BS]);
        }
        ode_f2(za, zb, ka, kb, sWo1t, sbo1, sWo2, sbo2);           // k4
        #pragma unroll
        for (int p = 0; p < 8; ++p){
            zpa[p*BS] = fma2(sdt, add2(ksa[p], ka[p]), zpa[p*BS]);
            zpb[p*BS] = fma2(sdt, add2(ksb[p], kb[p]), zpb[p*BS]);
        }
    }
}

extern "C" void kernel_launch(void* const* d_in, const int* in_sizes, int n_in,
                              void* d_out, int out_size)
{
    const float* x0  = (const float*)d_in[0];
    const float* ts  = (const float*)d_in[1];
    const float* We1 = (const float*)d_in[2];
    const float* be1 = (const float*)d_in[3];
    const float* We2 = (const float*)d_in[4];
    const float* be2 = (const float*)d_in[5];
    const float* Wo1 = (const float*)d_in[6];
    const float* bo1 = (const float*)d_in[7];
    const float* Wo2 = (const float*)d_in[8];
    const float* bo2 = (const float*)d_in[9];
    const float* Wd1 = (const float*)d_in[10];
    const float* bd1 = (const float*)d_in[11];
    const float* Wd2 = (const float*)d_in[12];
    const float* bd2 = (const float*)d_in[13];

    const int B = in_sizes[0] / 2;   // (B, 2)
    const int T = in_sizes[1];       // (T,)
    const int half = B / 2;          // 2 elements per thread
    const int grid = (half + BS - 1) / BS;

    node_kernel<<<grid, BS>>>(x0, ts, We1, be1, We2, be2, Wo1, bo1,
                              Wo2, bo2, Wd1, bd1, Wd2, bd2,
                              (float*)d_out, B, T);
}

// round 8
// speedup vs baseline: 1.7689x; 1.6520x over previous
#include <cuda_runtime.h>

typedef unsigned long long u64;

#define LAT    16
#define HID    50
#define HIDP   52          // hidden padded to multiple of 4
#define NQ     (HIDP/4)    // 13
#define TSMAX  132
#define BS     32          // threads per CTA (1 warp)
#define TANH_C 2.88539008177792681472f   // 2*log2(e)

// ---- packed f32x2 helpers (sm_100+; PTX-only) ----
static __device__ __forceinline__ u64 pk(float lo, float hi){
    u64 r; asm("mov.b64 %0, {%1,%2};" : "=l"(r) : "f"(lo), "f"(hi)); return r;
}
static __device__ __forceinline__ void upk(u64 v, float& lo, float& hi){
    asm("mov.b64 {%0,%1}, %2;" : "=f"(lo), "=f"(hi) : "l"(v));
}
static __device__ __forceinline__ u64 dup2(float x){ return pk(x, x); }
static __device__ __forceinline__ u64 fma2(u64 a, u64 b, u64 c){
    u64 d; asm("fma.rn.f32x2 %0, %1, %2, %3;" : "=l"(d) : "l"(a), "l"(b), "l"(c)); return d;
}
static __device__ __forceinline__ u64 add2(u64 a, u64 b){
    u64 d; asm("add.rn.f32x2 %0, %1, %2;" : "=l"(d) : "l"(a), "l"(b)); return d;
}
static __device__ __forceinline__ float hsum(u64 v){
    float lo, hi; upk(v, lo, hi); return lo + hi;
}

// tanh from PRE-SCALED argument a = 2*log2(e)*x : tanh(x) = 1 - 2/(2^a + 1)
static __device__ __forceinline__ float tanh_pre(float a){
    float e, r;
    asm("ex2.approx.f32 %0, %1;" : "=f"(e) : "f"(a));
    const float d = e + 1.0f;
    asm("rcp.approx.f32 %0, %1;" : "=f"(r) : "f"(d));
    return fmaf(-2.0f, r, 1.0f);
}

// Dual-element ODE func: o = tanh(z @ W1 + b1) @ W2 + b2 for two states,
// sharing every weight load. W1t pre-scaled by TANH_C; b1 packed as (b*C, 0)
// pairs so the bias rides inside the packed partial (hsum -> biased scaled act).
static __device__ __forceinline__ void ode_f2(
    const u64* __restrict__ za, const u64* __restrict__ zb,
    u64* __restrict__ oa, u64* __restrict__ ob,
    const float* __restrict__ sW1t,   // [HIDP][LAT] transposed, scaled
    const u64*  __restrict__ sb1p,    // [HIDP] packed (b*C, 0)
    const float* __restrict__ sW2,    // [HIDP][LAT]
    const float* __restrict__ sb2)    // [LAT]
{
    #pragma unroll
    for (int p = 0; p < 8; ++p){ oa[p] = *(const u64*)(sb2 + 2*p); ob[p] = oa[p]; }

    #pragma unroll 1
    for (int lq = 0; lq < NQ; ++lq){
        const int l = lq * 4;
        const ulonglong2 bp01 = *(const ulonglong2*)(sb1p + l);
        const ulonglong2 bp23 = *(const ulonglong2*)(sb1p + l + 2);
        u64 pa0 = bp01.x, pa1 = bp01.y, pa2 = bp23.x, pa3 = bp23.y;
        u64 pb0 = 0, pb1 = 0, pb2 = 0, pb3 = 0;
        const float* r = sW1t + l*LAT;
        #pragma unroll
        for (int q = 0; q < 4; ++q){
            const ulonglong2 w0 = *(const ulonglong2*)(r           + 4*q);
            const ulonglong2 w1 = *(const ulonglong2*)(r +   LAT   + 4*q);
            const ulonglong2 w2 = *(const ulonglong2*)(r + 2*LAT   + 4*q);
            const ulonglong2 w3 = *(const ulonglong2*)(r + 3*LAT   + 4*q);
            pa0 = fma2(za[2*q], w0.x, pa0); pa0 = fma2(za[2*q+1], w0.y, pa0);
            pb0 = fma2(zb[2*q], w0.x, pb0); pb0 = fma2(zb[2*q+1], w0.y, pb0);
            pa1 = fma2(za[2*q], w1.x, pa1); pa1 = fma2(za[2*q+1], w1.y, pa1);
            pb1 = fma2(zb[2*q], w1.x, pb1); pb1 = fma2(zb[2*q+1], w1.y, pb1);
            pa2 = fma2(za[2*q], w2.x, pa2); pa2 = fma2(za[2*q+1], w2.y, pa2);
            pb2 = fma2(zb[2*q], w2.x, pb2); pb2 = fma2(zb[2*q+1], w2.y, pb2);
            pa3 = fma2(za[2*q], w3.x, pa3); pa3 = fma2(za[2*q+1], w3.y, pa3);
            pb3 = fma2(zb[2*q], w3.x, pb3); pb3 = fma2(zb[2*q+1], w3.y, pb3);
        }
        // elem-b partials were seeded with 0; add the biased a-seed symmetry:
        // pb accumulators need the same bias -> fold via hsum(pb)+bias_lo trick:
        float ha[4], hb[4];
        float blo0, bz0, blo1, bz1, blo2, bz2, blo3, bz3;
        upk(bp01.x, blo0, bz0); upk(bp01.y, blo1, bz1);
        upk(bp23.x, blo2, bz2); upk(bp23.y, blo3, bz3);
        ha[0] = tanh_pre(hsum(pa0));          hb[0] = tanh_pre(hsum(pb0) + blo0);
        ha[1] = tanh_pre(hsum(pa1));          hb[1] = tanh_pre(hsum(pb1) + blo1);
        ha[2] = tanh_pre(hsum(pa2));          hb[2] = tanh_pre(hsum(pb2) + blo2);
        ha[3] = tanh_pre(hsum(pa3));          hb[3] = tanh_pre(hsum(pb3) + blo3);
        #pragma unroll
        for (int r4 = 0; r4 < 4; ++r4){
            const u64 hda = dup2(ha[r4]);
            const u64 hdb = dup2(hb[r4]);
            const float* wr = sW2 + (l + r4)*LAT;
            #pragma unroll
            for (int q = 0; q < 4; ++q){
                const ulonglong2 w = *(const ulonglong2*)(wr + 4*q);
                oa[2*q]     = fma2(hda, w.x, oa[2*q]);
                oa[2*q + 1] = fma2(hda, w.y, oa[2*q + 1]);
                ob[2*q]     = fma2(hdb, w.x, ob[2*q]);
                ob[2*q + 1] = fma2(hdb, w.y, ob[2*q + 1]);
            }
        }
    }
}

// Dual-element decoder: y = relu(z @ Wd1 + bd1) @ Wd2 + bd2 (bias-packed, unscaled)
static __device__ __forceinline__ void dec_f2(
    const u64* __restrict__ za, const u64* __restrict__ zb,
    float& ya, float& yb,
    const float* __restrict__ sW1t, const u64* __restrict__ sb1p,
    const float* __restrict__ sw2, float b2)
{
    ya = b2; yb = b2;
    #pragma unroll 1
    for (int lq = 0; lq < NQ; ++lq){
        const int l = lq * 4;
        const ulonglong2 bp01 = *(const ulonglong2*)(sb1p + l);
        const ulonglong2 bp23 = *(const ulonglong2*)(sb1p + l + 2);
        u64 pa0 = bp01.x, pa1 = bp01.y, pa2 = bp23.x, pa3 = bp23.y;
        u64 pb0 = 0, pb1 = 0, pb2 = 0, pb3 = 0;
        const float* r = sW1t + l*LAT;
        #pragma unroll
        for (int q = 0; q < 4; ++q){
            const ulonglong2 w0 = *(const ulonglong2*)(r           + 4*q);
            const ulonglong2 w1 = *(const ulonglong2*)(r +   LAT   + 4*q);
            const ulonglong2 w2 = *(const ulonglong2*)(r + 2*LAT   + 4*q);
            const ulonglong2 w3 = *(const ulonglong2*)(r + 3*LAT   + 4*q);
            pa0 = fma2(za[2*q], w0.x, pa0); pa0 = fma2(za[2*q+1], w0.y, pa0);
            pb0 = fma2(zb[2*q], w0.x, pb0); pb0 = fma2(zb[2*q+1], w0.y, pb0);
            pa1 = fma2(za[2*q], w1.x, pa1); pa1 = fma2(za[2*q+1], w1.y, pa1);
            pb1 = fma2(zb[2*q], w1.x, pb1); pb1 = fma2(zb[2*q+1], w1.y, pb1);
            pa2 = fma2(za[2*q], w2.x, pa2); pa2 = fma2(za[2*q+1], w2.y, pa2);
            pb2 = fma2(zb[2*q], w2.x, pb2); pb2 = fma2(zb[2*q+1], w2.y, pb2);
            pa3 = fma2(za[2*q], w3.x, pa3); pa3 = fma2(za[2*q+1], w3.y, pa3);
            pb3 = fma2(zb[2*q], w3.x, pb3); pb3 = fma2(zb[2*q+1], w3.y, pb3);
        }
        float blo0, z0, blo1, z1, blo2, z2, blo3, z3;
        upk(bp01.x, blo0, z0); upk(bp01.y, blo1, z1);
        upk(bp23.x, blo2, z2); upk(bp23.y, blo3, z3);
        const float4 w2 = *(const float4*)(sw2 + l);
        ya = fmaf(fmaxf(hsum(pa0), 0.f), w2.x, ya);
        yb = fmaf(fmaxf(hsum(pb0) + blo0, 0.f), w2.x, yb);
        ya = fmaf(fmaxf(hsum(pa1), 0.f), w2.y, ya);
        yb = fmaf(fmaxf(hsum(pb1) + blo1, 0.f), w2.y, yb);
        ya = fmaf(fmaxf(hsum(pa2), 0.f), w2.z, ya);
        yb = fmaf(fmaxf(hsum(pb2) + blo2, 0.f), w2.z, yb);
        ya = fmaf(fmaxf(hsum(pa3), 0.f), w2.w, ya);
        yb = fmaf(fmaxf(hsum(pb3) + blo3, 0.f), w2.w, yb);
    }
}

__global__ void __launch_bounds__(BS) node_kernel(
    const float* __restrict__ x0,  const float* __restrict__ ts,
    const float* __restrict__ We1, const float* __restrict__ be1,
    const float* __restrict__ We2, const float* __restrict__ be2,
    const float* __restrict__ Wo1, const float* __restrict__ bo1,
    const float* __restrict__ Wo2, const float* __restrict__ bo2,
    const float* __restrict__ Wd1, const float* __restrict__ bd1,
    const float* __restrict__ Wd2, const float* __restrict__ bd2,
    float* __restrict__ out, int B, int T)
{
    __shared__ __align__(16) float sWo1t[HIDP*LAT];  // [l][i] transposed, *TANH_C
    __shared__ __align__(16) float sWo2 [HIDP*LAT];  // [l][j]
    __shared__ __align__(16) float sWd1t[HIDP*LAT];  // [l][i] transposed
    __shared__ __align__(16) float sWe2 [HIDP*LAT];  // [l][j]
    __shared__ __align__(16) float sWe1 [2*HIDP];
    __shared__ __align__(16) u64   sbo1p[HIDP];      // (bo1*C, 0) pairs
    __shared__ __align__(16) u64   sbd1p[HIDP];      // (bd1, 0) pairs
    __shared__ __align__(16) float sbe1 [HIDP];
    __shared__ __align__(16) float sWd2 [HIDP];
    __shared__ __align__(16) float sbo2 [LAT];
    __shared__ __align__(16) float sbe2 [LAT];
    __shared__ __align__(16) u64   sZ [16*BS];       // per-thread z state (2 elems)
    __shared__ __align__(16) u64   sKs[16*BS];       // per-thread RK accumulator
    __shared__ float sT[TSMAX];

    const int tid = threadIdx.x;

    for (int idx = tid; idx < HIDP*LAT; idx += BS){
        const int l = idx / LAT, i = idx - l*LAT;
        const bool v = (l < HID);
        sWo1t[idx] = v ? Wo1[i*HID + l] * TANH_C : 0.f;   // transpose + prescale
        sWd1t[idx] = v ? Wd1[i*HID + l] : 0.f;            // transpose
        sWo2 [idx] = v ? Wo2[l*LAT + i] : 0.f;
        sWe2 [idx] = v ? We2[l*LAT + i] : 0.f;
    }
    for (int idx = tid; idx < HIDP; idx += BS){
        const bool v = (idx < HID);
        sbo1p[idx] = v ? pk(bo1[idx] * TANH_C, 0.f) : 0ull;
        sbd1p[idx] = v ? pk(bd1[idx], 0.f) : 0ull;
        sbe1[idx] = v ? be1[idx] : 0.f;
        sWd2[idx] = v ? Wd2[idx] : 0.f;
        sWe1[idx]        = v ? We1[idx]       : 0.f;  // row 0 of (2,HID)
        sWe1[HIDP + idx] = v ? We1[HID + idx] : 0.f;  // row 1
    }
    if (tid < LAT){ sbo2[tid] = bo2[tid]; sbe2[tid] = be2[tid]; }
    const int tcap = (T < TSMAX) ? T : TSMAX;
    for (int idx = tid; idx < tcap; idx += BS) sT[idx] = ts[idx];
    __syncthreads();

    const int half = B >> 1;
    const int b0 = blockIdx.x * BS + tid;
    if (b0 >= half) return;
    const int b1 = b0 + half;

    u64* zA = &sZ[tid];             // elem-a state p at zA[p*BS]
    u64* zB = &sZ[8*BS + tid];
    u64* kA = &sKs[tid];
    u64* kB = &sKs[8*BS + tid];

    // ---- encoder for both elements (shared weight loads) ----
    {
        const float2 xa = *(const float2*)(x0 + 2*b0);
        const float2 xb = *(const float2*)(x0 + 2*b1);
        u64 ea[8], eb[8];
        #pragma unroll
        for (int p = 0; p < 8; ++p){ ea[p] = *(const u64*)(sbe2 + 2*p); eb[p] = ea[p]; }
        #pragma unroll 1
        for (int l = 0; l < HID; ++l){
            const float w0 = sWe1[l], w1 = sWe1[HIDP + l], bb = sbe1[l];
            const float hA = fmaxf(fmaf(xa.x, w0, fmaf(xa.y, w1, bb)), 0.f);
            const float hB = fmaxf(fmaf(xb.x, w0, fmaf(xb.y, w1, bb)), 0.f);
            const u64 hda = dup2(hA), hdb = dup2(hB);
            const float* wr = sWe2 + l*LAT;
            #pragma unroll
            for (int q = 0; q < 4; ++q){
                const ulonglong2 w2 = *(const ulonglong2*)(wr + 4*q);
                ea[2*q]     = fma2(hda, w2.x, ea[2*q]);
                ea[2*q + 1] = fma2(hda, w2.y, ea[2*q + 1]);
                eb[2*q]     = fma2(hdb, w2.x, eb[2*q]);
                eb[2*q + 1] = fma2(hdb, w2.y, eb[2*q + 1]);
            }
        }
        #pragma unroll
        for (int p = 0; p < 8; ++p){ zA[p*BS] = ea[p]; zB[p*BS] = eb[p]; }
    }

    u64 za[8], zb[8], ka[8], kb[8];
    const float bd2v = bd2[0];
    const u64 two = dup2(2.0f);

    #pragma unroll 1
    for (int t = 0; t < T; ++t){
        #pragma unroll
        for (int p = 0; p < 8; ++p){ za[p] = zA[p*BS]; zb[p] = zB[p*BS]; }

        float ya, yb;
        dec_f2(za, zb, ya, yb, sWd1t, sbd1p, sWd2, bd2v);
        out[(size_t)t * B + b0] = ya;
        out[(size_t)t * B + b1] = yb;
        if (t == T - 1) break;

        const float dt = (t + 1 < tcap) ? (sT[t+1] - sT[t]) : (ts[t+1] - ts[t]);
        const u64 hdt = dup2(0.5f * dt);
        const u64 fdt = dup2(dt);
        const u64 sdt = dup2(dt * (1.0f/6.0f));

        ode_f2(za, zb, ka, kb, sWo1t, sbo1p, sWo2, sbo2);          // k1
        #pragma unroll
        for (int p = 0; p < 8; ++p){
            kA[p*BS] = ka[p];                      kB[p*BS] = kb[p];
            za[p] = fma2(hdt, ka[p], zA[p*BS]);    zb[p] = fma2(hdt, kb[p], zB[p*BS]);
        }
        ode_f2(za, zb, ka, kb, sWo1t, sbo1p, sWo2, sbo2);          // k2
        #pragma unroll
        for (int p = 0; p < 8; ++p){
            kA[p*BS] = fma2(two, ka[p], kA[p*BS]); kB[p*BS] = fma2(two, kb[p], kB[p*BS]);
            za[p] = fma2(hdt, ka[p], zA[p*BS]);    zb[p] = fma2(hdt, kb[p], zB[p*BS]);
        }
        ode_f2(za, zb, ka, kb, sWo1t, sbo1p, sWo2, sbo2);          // k3
        #pragma unroll
        for (int p = 0; p < 8; ++p){
            kA[p*BS] = fma2(two, ka[p], kA[p*BS]); kB[p*BS] = fma2(two, kb[p], kB[p*BS]);
            za[p] = fma2(fdt, ka[p], zA[p*BS]);    zb[p] = fma2(fdt, kb[p], zB[p*BS]);
        }
        ode_f2(za, zb, ka, kb, sWo1t, sbo1p, sWo2, sbo2);          // k4
        #pragma unroll
        for (int p = 0; p < 8; ++p){
            zA[p*BS] = fma2(sdt, add2(kA[p*BS], ka[p]), zA[p*BS]);
            zB[p*BS] = fma2(sdt, add2(kB[p*BS], kb[p]), zB[p*BS]);
        }
    }
}

extern "C" void kernel_launch(void* const* d_in, const int* in_sizes, int n_in,
                              void* d_out, int out_size)
{
    const float* x0  = (const float*)d_in[0];
    const float* ts  = (const float*)d_in[1];
    const float* We1 = (const float*)d_in[2];
    const float* be1 = (const float*)d_in[3];
    const float* We2 = (const float*)d_in[4];
    const float* be2 = (const float*)d_in[5];
    const float* Wo1 = (const float*)d_in[6];
    const float* bo1 = (const float*)d_in[7];
    const float* Wo2 = (const float*)d_in[8];
    const float* bo2 = (const float*)d_in[9];
    const float* Wd1 = (const float*)d_in[10];
    const float* bd1 = (const float*)d_in[11];
    const float* Wd2 = (const float*)d_in[12];
    const float* bd2 = (const float*)d_in[13];

    const int B = in_sizes[0] / 2;   // (B, 2)
    const int T = in_sizes[1];       // (T,)
    const int half = B / 2;          // 2 elements per thread
    const int grid = (half + BS - 1) / BS;

    node_kernel<<<grid, BS>>>(x0, ts, We1, be1, We2, be2, Wo1, bo1,
                              Wo2, bo2, Wd1, bd1, Wd2, bd2,
                              (float*)d_out, B, T);
}